// round 15
// baseline (speedup 1.0000x reference)
#include <cuda_runtime.h>
#include <cuda_bf16.h>
#include <cuda_fp16.h>
#include <math.h>
#include <stdint.h>

#define NN   100000
#define NE   1600000
#define INF  16
#define HIDD 128
#define NL   8
#define NB_SCAN 391    /* ceil(NN/256) */
#define NT64  1563     /* ceil(NN/64) */

// ---------------- device scratch ----------------
__device__ __align__(16) __half g_hh[NN * HIDD];   // post-activation h (fp16)
__device__ __align__(16) __half g_zh[NN * HIDD];   // raw GEMM<1> output (fp16)
__device__ __align__(16) float g_y1[NN * HIDD];
__device__ __align__(16) float g_skip[NN * HIDD];
__device__ __align__(16) float g_za[NN * HIDD];    // agg output
__device__ __align__(16) float g_z0[NN * INF];
__device__ int   g_deg[NN];
__device__ int   g_row[NN];
__device__ int   g_fill[NN];
__device__ int   g_csr[NE];
__device__ int   g_bsum[512];
// BN stats slots: i (0..7)=inner BN layer i, 8+i=outer BN layer i, 16=regressor
__device__ __align__(16) float g_st[17 * 256];
#define BIMG 17408
__device__ __align__(16) __nv_bfloat16 g_Bh[17 * BIMG];
__device__ __align__(16) __nv_bfloat16 g_Bl[17 * BIMG];

__device__ __forceinline__ float4 f4ld(const float* p) { return *(const float4*)p; }

__device__ __forceinline__ uint32_t smem_u32(const void* p) {
    uint32_t a;
    asm("{ .reg .u64 t; cvta.to.shared.u64 t, %1; cvt.u32.u64 %0, t; }" : "=r"(a) : "l"(p));
    return a;
}
__device__ __forceinline__ uint32_t pk(__nv_bfloat16 a, __nv_bfloat16 b) {
    __nv_bfloat162 t(a, b);
    return *(uint32_t*)&t;
}

#define LDM4(r, addr) \
    asm volatile("ldmatrix.sync.aligned.m8n8.x4.shared.b16 {%0,%1,%2,%3}, [%4];" \
        : "=r"((r)[0]), "=r"((r)[1]), "=r"((r)[2]), "=r"((r)[3]) : "r"(addr))

#define MMA16(acc, a, b0, b1) \
    asm volatile("mma.sync.aligned.m16n8k16.row.col.f32.bf16.bf16.f32 " \
        "{%0,%1,%2,%3}, {%4,%5,%6,%7}, {%8,%9}, {%0,%1,%2,%3};" \
        : "+f"((acc)[0]), "+f"((acc)[1]), "+f"((acc)[2]), "+f"((acc)[3]) \
        : "r"((a)[0]), "r"((a)[1]), "r"((a)[2]), "r"((a)[3]), "r"(b0), "r"(b1))

__device__ __forceinline__ void bn_coef(int slot, int t, const float* gamma,
                                        const float* beta, float& sc, float& sh) {
    float su = g_st[slot * 256 + t];
    float sq = g_st[slot * 256 + 128 + t];
    float mean = su * (1.f / NN);
    float var = sq * (1.f / NN) - mean * mean;
    float rstd = rsqrtf(fmaxf(var, 0.f) + 1e-5f);
    sc = __ldg(&gamma[t]) * rstd;
    sh = __ldg(&beta[t]) - mean * sc;
}

// ---------------- CSR build ----------------
__global__ void k_zero() {
    int i = blockIdx.x * blockDim.x + threadIdx.x;
    if (i < NN) g_deg[i] = 0;
    if (i < 17 * 256) g_st[i] = 0.f;
}
__global__ void k_hist(const int* __restrict__ dst) {
    int e = blockIdx.x * blockDim.x + threadIdx.x;
    if (e < NE) atomicAdd(&g_deg[dst[e]], 1);
}
__global__ void k_scan1() {
    __shared__ int sh[256];
    int t = threadIdx.x;
    int i = blockIdx.x * 256 + t;
    int v = (i < NN) ? g_deg[i] : 0;
    sh[t] = v;
    __syncthreads();
    #pragma unroll
    for (int off = 1; off < 256; off <<= 1) {
        int add = (t >= off) ? sh[t - off] : 0;
        __syncthreads();
        sh[t] += add;
        __syncthreads();
    }
    if (i < NN) g_row[i] = sh[t] - v;
    if (t == 255) g_bsum[blockIdx.x] = sh[255];
}
__global__ void k_scan2() {
    __shared__ int sh[512];
    int t = threadIdx.x;
    int v = (t < NB_SCAN) ? g_bsum[t] : 0;
    sh[t] = v;
    __syncthreads();
    #pragma unroll
    for (int off = 1; off < 512; off <<= 1) {
        int add = (t >= off) ? sh[t - off] : 0;
        __syncthreads();
        sh[t] += add;
        __syncthreads();
    }
    g_bsum[t] = sh[t] - v;
}
__global__ void k_scan3() {
    int i = blockIdx.x * blockDim.x + threadIdx.x;
    if (i < NN) {
        int rs = g_row[i] + g_bsum[i >> 8];
        g_row[i] = rs;
        g_fill[i] = rs;
    }
}
__global__ void k_fill(const int* __restrict__ src, const int* __restrict__ dst) {
    int e = blockIdx.x * blockDim.x + threadIdx.x;
    if (e < NE) {
        int d = dst[e];
        int p = atomicAdd(&g_fill[d], 1);
        g_csr[p] = src[e];
    }
}

// ---------------- weight prep ----------------
__global__ void k_prepw(const float* __restrict__ W1_0, const float* __restrict__ W1,
                        const float* __restrict__ W2, const float* __restrict__ Wr1) {
    int img = blockIdx.y;
    int idx = blockIdx.x * 256 + threadIdx.x;
    if (idx >= BIMG) return;
    int n = idx / 136;
    int k = idx % 136;
    int Kreal = (img == 0) ? 16 : 128;
    const float* W = (img == 0) ? W1_0
                   : (img <= 7) ? (W1 + (size_t)(img - 1) * 16384)
                   : (img <= 15) ? (W2 + (size_t)(img - 8) * 16384)
                   : Wr1;
    float w = (k < Kreal) ? W[(size_t)k * 128 + n] : 0.f;
    __nv_bfloat16 hi = __float2bfloat16_rn(w);
    __nv_bfloat16 lo = __float2bfloat16_rn(w - __bfloat162float(hi));
    g_Bh[(size_t)img * BIMG + idx] = hi;
    g_Bl[(size_t)img * BIMG + idx] = lo;
}

// ---------------- aggregation: warp/node, uint2, 2-edge unroll + idx prefetch ----------------
__global__ void k_agg(const __half* __restrict__ hin, float* __restrict__ zout,
                      const float* __restrict__ eps, int layer) {
    int gt = blockIdx.x * blockDim.x + threadIdx.x;
    int node = gt >> 5;
    int lane = gt & 31;
    if (node >= NN) return;
    float e1 = 1.f + __ldg(&eps[layer]);
    const uint2* h2 = (const uint2*)hin;
    int start = g_row[node];
    int d = g_deg[node];

    uint2 ua = h2[(size_t)node * 32 + lane];
    float2 a0 = __half22float2(*(__half2*)&ua.x);
    float2 a1 = __half22float2(*(__half2*)&ua.y);
    float4 acc0 = make_float4(a0.x * e1, a0.y * e1, a1.x * e1, a1.y * e1);
    float4 acc1 = make_float4(0.f, 0.f, 0.f, 0.f);

    int s0 = 0, s1 = 0;
    if (d >= 2) {
        s0 = __ldg(&g_csr[start]);
        s1 = __ldg(&g_csr[start + 1]);
    }
    int j = 0;
    for (; j + 2 <= d; ) {
        int jn = j + 2;
        int n0 = 0, n1 = 0;
        if (jn + 2 <= d) {                       // warp-uniform predicate
            n0 = __ldg(&g_csr[start + jn]);
            n1 = __ldg(&g_csr[start + jn + 1]);
        }
        uint2 u0 = h2[(size_t)s0 * 32 + lane];
        uint2 u1 = h2[(size_t)s1 * 32 + lane];
        float2 v00 = __half22float2(*(__half2*)&u0.x);
        float2 v01 = __half22float2(*(__half2*)&u0.y);
        float2 v10 = __half22float2(*(__half2*)&u1.x);
        float2 v11 = __half22float2(*(__half2*)&u1.y);
        acc0.x += v00.x; acc0.y += v00.y; acc0.z += v01.x; acc0.w += v01.y;
        acc1.x += v10.x; acc1.y += v10.y; acc1.z += v11.x; acc1.w += v11.y;
        s0 = n0; s1 = n1;
        j = jn;
    }
    if (j < d) {
        int s = __ldg(&g_csr[start + j]);
        uint2 u = h2[(size_t)s * 32 + lane];
        float2 v0 = __half22float2(*(__half2*)&u.x);
        float2 v1 = __half22float2(*(__half2*)&u.y);
        acc0.x += v0.x; acc0.y += v0.y; acc0.z += v1.x; acc0.w += v1.y;
    }
    ((float4*)zout)[(size_t)node * 32 + lane] =
        make_float4(acc0.x + acc1.x, acc0.y + acc1.y, acc0.z + acc1.z, acc0.w + acc1.w);
}

__global__ void k_agg0(const float* __restrict__ x, float* __restrict__ z0,
                       const float* __restrict__ eps) {
    int t = blockIdx.x * blockDim.x + threadIdx.x;
    if (t >= NN * 4) return;
    int n = t >> 2;
    float e1 = 1.f + __ldg(&eps[0]);
    const float4* x4 = (const float4*)x;
    float4 a = x4[t];
    float4 acc = make_float4(a.x * e1, a.y * e1, a.z * e1, a.w * e1);
    int start = g_row[n];
    int d = g_deg[n];
    int q = t & 3;
    for (int j = 0; j < d; j++) {
        int s = __ldg(&g_csr[start + j]);
        float4 v = x4[(size_t)s * 4 + q];
        acc.x += v.x; acc.y += v.y; acc.z += v.z; acc.w += v.w;
    }
    ((float4*)z0)[t] = acc;
}

// ---------------- post: reads fp16 z; h(fp16) = relu(bn(z)); optional skip ----------------
__global__ void k_post(const __half* __restrict__ y, __half* __restrict__ h, int skipmode,
                       const float* __restrict__ gamma, const float* __restrict__ beta,
                       int slot) {
    __shared__ float ssc[128], ssh[128];
    int tid = threadIdx.x;
    if (tid < 128) {
        float sc, sh;
        bn_coef(slot, tid, gamma, beta, sc, sh);
        ssc[tid] = sc;
        ssh[tid] = sh;
    }
    __syncthreads();
    int i = blockIdx.x * blockDim.x + tid;
    if (i >= NN * 32) return;
    int c4 = (i & 31) * 4;
    float4 sc = *(float4*)(ssc + c4);
    float4 sh = *(float4*)(ssh + c4);
    uint2 u = ((const uint2*)y)[i];
    float2 za = __half22float2(*(__half2*)&u.x);
    float2 zb = __half22float2(*(__half2*)&u.y);
    float4 v;
    v.x = fmaxf(fmaf(za.x, sc.x, sh.x), 0.f);
    v.y = fmaxf(fmaf(za.y, sc.y, sh.y), 0.f);
    v.z = fmaxf(fmaf(zb.x, sc.z, sh.z), 0.f);
    v.w = fmaxf(fmaf(zb.y, sc.w, sh.w), 0.f);
    __half2 p0 = __floats2half2_rn(v.x, v.y);
    __half2 p1 = __floats2half2_rn(v.z, v.w);
    ((uint2*)h)[i] = make_uint2(*(uint32_t*)&p0, *(uint32_t*)&p1);
    if (skipmode == 1) {
        ((float4*)g_skip)[i] = v;
    } else if (skipmode == 2) {
        float4 s = ((float4*)g_skip)[i];
        s.x += v.x; s.y += v.y; s.z += v.z; s.w += v.w;
        ((float4*)g_skip)[i] = s;
    }
}

// ---------------- mma.sync bf16x3 GEMM, persistent, M-tile=64, occupancy 2 ----------------
// MODE 0: identity; 1: relu(A*sc+sh) from slotIn; 2: A*0.25.  OUTH: C stored fp16.
#define SM_AH 0
#define SM_AL 17408
#define SM_BH 34816
#define SM_BL 69632
#define SM_BI 104448
#define SM_RD 104960
#define SM_SC 105984
#define SM_SH 106496
#define SMEM_MG 107008

template<int MODE, int KR, int OUTH>
__global__ void __launch_bounds__(256, 2)
k_mgemm(const float* __restrict__ A, const __nv_bfloat16* __restrict__ Bh,
        const __nv_bfloat16* __restrict__ Bl, const float* __restrict__ bias,
        void* __restrict__ Cv, const float* __restrict__ gamma,
        const float* __restrict__ beta, int slotIn, int slotOut) {
    extern __shared__ char smem[];
    uint32_t sb = smem_u32(smem);
    float* fs = (float*)smem;
    float* Cf = (float*)Cv;
    __half* Ch = (__half*)Cv;
    const int tid = threadIdx.x, lane = tid & 31, wid = tid >> 5;
    const int wm = wid >> 2, wn = wid & 3;   // wm in {0,1}: 32 rows each

    for (int i = tid * 16; i < 34816; i += 4096) {
        *(uint4*)(smem + SM_BH + i) = *(const uint4*)((const char*)Bh + i);
        *(uint4*)(smem + SM_BL + i) = *(const uint4*)((const char*)Bl + i);
    }
    if (tid < 128) {
        fs[(SM_BI >> 2) + tid] = __ldg(&bias[tid]);
        fs[(SM_RD >> 2) + tid] = 0.f;
        fs[(SM_RD >> 2) + 128 + tid] = 0.f;
        if (MODE == 1) {
            float sc, sh;
            bn_coef(slotIn, tid, gamma, beta, sc, sh);
            fs[(SM_SC >> 2) + tid] = sc;
            fs[(SM_SH >> 2) + tid] = sh;
        }
    }

    const uint32_t a_row = (lane & 7) + ((lane >> 3) & 1) * 8;
    const uint32_t a_kb  = (lane >> 4) * 16;
    const uint32_t b_n   = (lane & 7) + ((lane >> 4) & 1) * 8;
    const uint32_t b_kb  = ((lane >> 3) & 1) * 16;

    constexpr int F4R = KR / 4;
    constexpr int NIT = (64 * F4R) / 256;   // 8 for KR=128, 1 for KR=16

    float4 v[NIT];
    {
        int mb = blockIdx.x * 64;
        #pragma unroll
        for (int i = 0; i < NIT; i++) {
            int idx = tid + i * 256;
            int row = idx / F4R;
            int c = (idx % F4R) * 4;
            v[i] = make_float4(0.f, 0.f, 0.f, 0.f);
            if (mb + row < NN) v[i] = f4ld(A + (size_t)(mb + row) * KR + c);
        }
    }

    for (int tile = blockIdx.x; tile < NT64; tile += gridDim.x) {
        int mb = tile * 64;
        __syncthreads();

        #pragma unroll
        for (int i = 0; i < NIT; i++) {
            int idx = tid + i * 256;
            int row = idx / F4R;
            int c = (idx % F4R) * 4;
            float4 w = v[i];
            if (MODE == 1) {
                float4 sc = *(float4*)(fs + (SM_SC >> 2) + c);
                float4 sh = *(float4*)(fs + (SM_SH >> 2) + c);
                w.x = fmaxf(fmaf(w.x, sc.x, sh.x), 0.f);
                w.y = fmaxf(fmaf(w.y, sc.y, sh.y), 0.f);
                w.z = fmaxf(fmaf(w.z, sc.z, sh.z), 0.f);
                w.w = fmaxf(fmaf(w.w, sc.w, sh.w), 0.f);
            } else if (MODE == 2) {
                w.x *= 0.25f; w.y *= 0.25f; w.z *= 0.25f; w.w *= 0.25f;
            }
            if (MODE == 1 && mb + row >= NN) w = make_float4(0.f, 0.f, 0.f, 0.f);
            __nv_bfloat16 hx = __float2bfloat16_rn(w.x);
            __nv_bfloat16 hy = __float2bfloat16_rn(w.y);
            __nv_bfloat16 hz = __float2bfloat16_rn(w.z);
            __nv_bfloat16 hw = __float2bfloat16_rn(w.w);
            __nv_bfloat16 lx = __float2bfloat16_rn(w.x - __bfloat162float(hx));
            __nv_bfloat16 ly = __float2bfloat16_rn(w.y - __bfloat162float(hy));
            __nv_bfloat16 lz = __float2bfloat16_rn(w.z - __bfloat162float(hz));
            __nv_bfloat16 lw = __float2bfloat16_rn(w.w - __bfloat162float(hw));
            uint32_t off = (uint32_t)row * 272u + (uint32_t)c * 2u;
            *(uint2*)(smem + SM_AH + off) = make_uint2(pk(hx, hy), pk(hz, hw));
            *(uint2*)(smem + SM_AL + off) = make_uint2(pk(lx, ly), pk(lz, lw));
        }
        __syncthreads();

        int nt = tile + gridDim.x;
        if (nt < NT64) {
            int nmb = nt * 64;
            #pragma unroll
            for (int i = 0; i < NIT; i++) {
                int idx = tid + i * 256;
                int row = idx / F4R;
                int c = (idx % F4R) * 4;
                float4 nv = make_float4(0.f, 0.f, 0.f, 0.f);
                if (nmb + row < NN) nv = f4ld(A + (size_t)(nmb + row) * KR + c);
                v[i] = nv;
            }
        }

        float acc[2][4][4];
        #pragma unroll
        for (int mi = 0; mi < 2; mi++)
            #pragma unroll
            for (int ni = 0; ni < 4; ni++)
                #pragma unroll
                for (int r = 0; r < 4; r++) acc[mi][ni][r] = 0.f;

        #pragma unroll
        for (int ks = 0; ks < KR / 16; ks++) {
            uint32_t kb = ks * 32;
            uint32_t ah[2][4], al[2][4], bh2[2][4], bl2[2][4];
            #pragma unroll
            for (int mi = 0; mi < 2; mi++) {
                uint32_t addr = sb + SM_AH + (wm * 32 + mi * 16 + a_row) * 272 + a_kb + kb;
                LDM4(ah[mi], addr);
                LDM4(al[mi], addr + 17408);
            }
            #pragma unroll
            for (int g = 0; g < 2; g++) {
                uint32_t addr = sb + SM_BH + (wn * 32 + g * 16 + b_n) * 272 + b_kb + kb;
                LDM4(bh2[g], addr);
                LDM4(bl2[g], addr + 34816);
            }
            #pragma unroll
            for (int mi = 0; mi < 2; mi++)
                #pragma unroll
                for (int ni = 0; ni < 4; ni++) {
                    uint32_t b0h = bh2[ni >> 1][(ni & 1) * 2];
                    uint32_t b1h = bh2[ni >> 1][(ni & 1) * 2 + 1];
                    uint32_t b0l = bl2[ni >> 1][(ni & 1) * 2];
                    uint32_t b1l = bl2[ni >> 1][(ni & 1) * 2 + 1];
                    MMA16(acc[mi][ni], ah[mi], b0h, b1h);
                    MMA16(acc[mi][ni], al[mi], b0h, b1h);
                    MMA16(acc[mi][ni], ah[mi], b0l, b1l);
                }
        }

        float s0[4], s1[4], q0[4], q1[4];
        #pragma unroll
        for (int ni = 0; ni < 4; ni++) { s0[ni] = s1[ni] = q0[ni] = q1[ni] = 0.f; }
        #pragma unroll
        for (int mi = 0; mi < 2; mi++) {
            int row0 = mb + wm * 32 + mi * 16 + (lane >> 2);
            int row1 = row0 + 8;
            #pragma unroll
            for (int ni = 0; ni < 4; ni++) {
                int col = wn * 32 + ni * 8 + (lane & 3) * 2;
                float bb0 = fs[(SM_BI >> 2) + col];
                float bb1 = fs[(SM_BI >> 2) + col + 1];
                float v0 = acc[mi][ni][0] + bb0;
                float v1 = acc[mi][ni][1] + bb1;
                float v2 = acc[mi][ni][2] + bb0;
                float v3 = acc[mi][ni][3] + bb1;
                if (row0 < NN) {
                    if (OUTH) {
                        __half2 hv = __floats2half2_rn(v0, v1);
                        *(uint32_t*)(Ch + (size_t)row0 * 128 + col) = *(uint32_t*)&hv;
                    } else {
                        *(float2*)(Cf + (size_t)row0 * 128 + col) = make_float2(v0, v1);
                    }
                    s0[ni] += v0; s1[ni] += v1; q0[ni] += v0 * v0; q1[ni] += v1 * v1;
                }
                if (row1 < NN) {
                    if (OUTH) {
                        __half2 hv = __floats2half2_rn(v2, v3);
                        *(uint32_t*)(Ch + (size_t)row1 * 128 + col) = *(uint32_t*)&hv;
                    } else {
                        *(float2*)(Cf + (size_t)row1 * 128 + col) = make_float2(v2, v3);
                    }
                    s0[ni] += v2; s1[ni] += v3; q0[ni] += v2 * v2; q1[ni] += v3 * v3;
                }
            }
        }
        #pragma unroll
        for (int ni = 0; ni < 4; ni++) {
            #pragma unroll
            for (int off = 4; off < 32; off <<= 1) {
                s0[ni] += __shfl_xor_sync(0xffffffffu, s0[ni], off);
                s1[ni] += __shfl_xor_sync(0xffffffffu, s1[ni], off);
                q0[ni] += __shfl_xor_sync(0xffffffffu, q0[ni], off);
                q1[ni] += __shfl_xor_sync(0xffffffffu, q1[ni], off);
            }
            if (lane < 4) {
                int col = wn * 32 + ni * 8 + lane * 2;
                atomicAdd(&fs[(SM_RD >> 2) + col], s0[ni]);
                atomicAdd(&fs[(SM_RD >> 2) + col + 1], s1[ni]);
                atomicAdd(&fs[(SM_RD >> 2) + 128 + col], q0[ni]);
                atomicAdd(&fs[(SM_RD >> 2) + 128 + col + 1], q1[ni]);
            }
        }
    }
    __syncthreads();
    if (tid < 128) {
        atomicAdd(&g_st[slotOut * 256 + tid], fs[(SM_RD >> 2) + tid]);
        atomicAdd(&g_st[slotOut * 256 + 128 + tid], fs[(SM_RD >> 2) + 128 + tid]);
    }
}

// ---------------- final ----------------
__global__ void k_final(const float* __restrict__ y, const float* __restrict__ Wr2,
                        const float* __restrict__ br2, const float* __restrict__ gamma,
                        const float* __restrict__ beta, float* __restrict__ out) {
    __shared__ float w[128], ssc[128], ssh[128];
    int tid = threadIdx.x;
    if (tid < 128) {
        w[tid] = Wr2[tid];
        float sc, sh;
        bn_coef(16, tid, gamma, beta, sc, sh);
        ssc[tid] = sc;
        ssh[tid] = sh;
    }
    __syncthreads();
    int gt = blockIdx.x * blockDim.x + tid;
    int n = gt >> 5;
    int lane = gt & 31;
    if (n >= NN) return;
    float4 v = ((const float4*)y)[(size_t)n * 32 + lane];
    float4 sc = *(float4*)(ssc + lane * 4);
    float4 sh = *(float4*)(ssh + lane * 4);
    float d = fmaxf(fmaf(v.x, sc.x, sh.x), 0.f) * w[lane * 4 + 0]
            + fmaxf(fmaf(v.y, sc.y, sh.y), 0.f) * w[lane * 4 + 1]
            + fmaxf(fmaf(v.z, sc.z, sh.z), 0.f) * w[lane * 4 + 2]
            + fmaxf(fmaf(v.w, sc.w, sh.w), 0.f) * w[lane * 4 + 3];
    #pragma unroll
    for (int off = 16; off > 0; off >>= 1)
        d += __shfl_xor_sync(0xffffffffu, d, off);
    if (lane == 0) out[n] = 1.f / (1.f + expf(-(d + __ldg(br2))));
}

// ---------------- host ----------------
extern "C" void kernel_launch(void* const* d_in, const int* in_sizes, int n_in,
                              void* d_out, int out_size) {
    const float* x     = (const float*)d_in[0];
    const int*   ei    = (const int*)d_in[1];
    const float* eps   = (const float*)d_in[2];
    const float* W1_0  = (const float*)d_in[3];
    const float* b1_0  = (const float*)d_in[4];
    const float* W1    = (const float*)d_in[5];
    const float* b1    = (const float*)d_in[6];
    const float* g_in  = (const float*)d_in[7];
    const float* be_in = (const float*)d_in[8];
    const float* W2    = (const float*)d_in[9];
    const float* b2    = (const float*)d_in[10];
    const float* g_out = (const float*)d_in[11];
    const float* be_out= (const float*)d_in[12];
    const float* Wr1   = (const float*)d_in[13];
    const float* br1   = (const float*)d_in[14];
    const float* gr    = (const float*)d_in[15];
    const float* ber   = (const float*)d_in[16];
    const float* Wr2   = (const float*)d_in[17];
    const float* br2   = (const float*)d_in[18];
    const int* srcp = ei;
    const int* dstp = ei + NE;

    float *y1, *skip, *za, *z0;
    __half *hh, *zh;
    __nv_bfloat16 *bh, *bl;
    cudaGetSymbolAddress((void**)&hh, g_hh);
    cudaGetSymbolAddress((void**)&zh, g_zh);
    cudaGetSymbolAddress((void**)&y1, g_y1);
    cudaGetSymbolAddress((void**)&skip, g_skip);
    cudaGetSymbolAddress((void**)&za, g_za);
    cudaGetSymbolAddress((void**)&z0, g_z0);
    cudaGetSymbolAddress((void**)&bh, g_Bh);
    cudaGetSymbolAddress((void**)&bl, g_Bl);

    cudaFuncSetAttribute(k_mgemm<0,16,0>,  cudaFuncAttributeMaxDynamicSharedMemorySize, SMEM_MG);
    cudaFuncSetAttribute(k_mgemm<0,128,0>, cudaFuncAttributeMaxDynamicSharedMemorySize, SMEM_MG);
    cudaFuncSetAttribute(k_mgemm<1,128,1>, cudaFuncAttributeMaxDynamicSharedMemorySize, SMEM_MG);
    cudaFuncSetAttribute(k_mgemm<2,128,0>, cudaFuncAttributeMaxDynamicSharedMemorySize, SMEM_MG);

    const int GGRID = 296;   // 148 SMs x occupancy 2

    k_zero<<<(NN + 255) / 256, 256>>>();
    k_hist<<<(NE + 255) / 256, 256>>>(dstp);
    k_scan1<<<NB_SCAN, 256>>>();
    k_scan2<<<1, 512>>>();
    k_scan3<<<NB_SCAN, 256>>>();
    k_fill<<<(NE + 255) / 256, 256>>>(srcp, dstp);
    {
        dim3 g((BIMG + 255) / 256, 17);
        k_prepw<<<g, 256>>>(W1_0, W1, W2, Wr1);
    }

    for (int i = 0; i < NL; i++) {
        if (i == 0)
            k_agg0<<<(NN * 4 + 255) / 256, 256>>>(x, z0, eps);
        else
            k_agg<<<(NN * 32 + 255) / 256, 256>>>(hh, za, eps, i);

        const float* ba = (i == 0) ? b1_0 : (b1 + (size_t)(i - 1) * HIDD);
        int imgA = (i == 0) ? 0 : i;
        if (i == 0)
            k_mgemm<0,16,0><<<GGRID, 256, SMEM_MG>>>(z0, bh, bl, ba, y1,
                                                     (const float*)0, (const float*)0, 0, 0);
        else
            k_mgemm<0,128,0><<<GGRID, 256, SMEM_MG>>>(za, bh + (size_t)imgA * BIMG,
                                                      bl + (size_t)imgA * BIMG, ba, y1,
                                                      (const float*)0, (const float*)0, 0, i);

        int imgB = 8 + i;
        k_mgemm<1,128,1><<<GGRID, 256, SMEM_MG>>>(y1, bh + (size_t)imgB * BIMG,
                                                  bl + (size_t)imgB * BIMG,
                                                  b2 + (size_t)i * HIDD, zh,
                                                  g_in + (size_t)i * HIDD,
                                                  be_in + (size_t)i * HIDD, i, 8 + i);

        int sm = (i % 2 == 1) ? ((i == 1) ? 1 : 2) : 0;
        k_post<<<(NN * 32 + 255) / 256, 256>>>(zh, hh, sm,
                                               g_out + (size_t)i * HIDD,
                                               be_out + (size_t)i * HIDD, 8 + i);
    }

    // regressor
    k_mgemm<2,128,0><<<GGRID, 256, SMEM_MG>>>(skip, bh + (size_t)16 * BIMG,
                                              bl + (size_t)16 * BIMG, br1, y1,
                                              (const float*)0, (const float*)0, 0, 16);
    k_final<<<(NN * 32 + 255) / 256, 256>>>(y1, Wr2, br2, gr, ber, (float*)d_out);
}

// round 16
// speedup vs baseline: 1.1565x; 1.1565x over previous
#include <cuda_runtime.h>
#include <cuda_bf16.h>
#include <cuda_fp16.h>
#include <math.h>
#include <stdint.h>

#define NN   100000
#define NE   1600000
#define INF  16
#define HIDD 128
#define NL   8
#define NB_SCAN 391    /* ceil(NN/256) */
#define NT64  1563     /* ceil(NN/64) */

// ---------------- device scratch ----------------
__device__ __align__(16) __half g_hh[NN * HIDD];   // post-activation h (fp16)
__device__ __align__(16) __half g_zh[NN * HIDD];   // raw GEMM<1> output (fp16)
__device__ __align__(16) float g_y1[NN * HIDD];
__device__ __align__(16) float g_skip[NN * HIDD];
__device__ __align__(16) float g_za[NN * HIDD];    // agg output
__device__ __align__(16) float g_z0[NN * INF];
__device__ int   g_deg[NN];
__device__ int   g_row[NN];
__device__ int   g_fill[NN];
__device__ int   g_csr[NE];
__device__ int   g_bsum[512];
// BN stats slots: i (0..7)=inner BN layer i, 8+i=outer BN layer i, 16=regressor
__device__ __align__(16) float g_st[17 * 256];
#define BIMG 17408
__device__ __align__(16) __nv_bfloat16 g_Bh[17 * BIMG];
__device__ __align__(16) __nv_bfloat16 g_Bl[17 * BIMG];

__device__ __forceinline__ float4 f4ld(const float* p) { return *(const float4*)p; }

__device__ __forceinline__ uint32_t smem_u32(const void* p) {
    uint32_t a;
    asm("{ .reg .u64 t; cvta.to.shared.u64 t, %1; cvt.u32.u64 %0, t; }" : "=r"(a) : "l"(p));
    return a;
}
__device__ __forceinline__ uint32_t pk(__nv_bfloat16 a, __nv_bfloat16 b) {
    __nv_bfloat162 t(a, b);
    return *(uint32_t*)&t;
}

#define LDM4(r, addr) \
    asm volatile("ldmatrix.sync.aligned.m8n8.x4.shared.b16 {%0,%1,%2,%3}, [%4];" \
        : "=r"((r)[0]), "=r"((r)[1]), "=r"((r)[2]), "=r"((r)[3]) : "r"(addr))

#define MMA16(acc, a, b0, b1) \
    asm volatile("mma.sync.aligned.m16n8k16.row.col.f32.bf16.bf16.f32 " \
        "{%0,%1,%2,%3}, {%4,%5,%6,%7}, {%8,%9}, {%0,%1,%2,%3};" \
        : "+f"((acc)[0]), "+f"((acc)[1]), "+f"((acc)[2]), "+f"((acc)[3]) \
        : "r"((a)[0]), "r"((a)[1]), "r"((a)[2]), "r"((a)[3]), "r"(b0), "r"(b1))

__device__ __forceinline__ void bn_coef(int slot, int t, const float* gamma,
                                        const float* beta, float& sc, float& sh) {
    float su = g_st[slot * 256 + t];
    float sq = g_st[slot * 256 + 128 + t];
    float mean = su * (1.f / NN);
    float var = sq * (1.f / NN) - mean * mean;
    float rstd = rsqrtf(fmaxf(var, 0.f) + 1e-5f);
    sc = __ldg(&gamma[t]) * rstd;
    sh = __ldg(&beta[t]) - mean * sc;
}

// ---------------- CSR build ----------------
__global__ void k_zero() {
    int i = blockIdx.x * blockDim.x + threadIdx.x;
    if (i < NN) g_deg[i] = 0;
    if (i < 17 * 256) g_st[i] = 0.f;
}
__global__ void k_hist(const int* __restrict__ dst) {
    int e = blockIdx.x * blockDim.x + threadIdx.x;
    if (e < NE) atomicAdd(&g_deg[dst[e]], 1);
}
__global__ void k_scan1() {
    __shared__ int sh[256];
    int t = threadIdx.x;
    int i = blockIdx.x * 256 + t;
    int v = (i < NN) ? g_deg[i] : 0;
    sh[t] = v;
    __syncthreads();
    #pragma unroll
    for (int off = 1; off < 256; off <<= 1) {
        int add = (t >= off) ? sh[t - off] : 0;
        __syncthreads();
        sh[t] += add;
        __syncthreads();
    }
    if (i < NN) g_row[i] = sh[t] - v;
    if (t == 255) g_bsum[blockIdx.x] = sh[255];
}
__global__ void k_scan2() {
    __shared__ int sh[512];
    int t = threadIdx.x;
    int v = (t < NB_SCAN) ? g_bsum[t] : 0;
    sh[t] = v;
    __syncthreads();
    #pragma unroll
    for (int off = 1; off < 512; off <<= 1) {
        int add = (t >= off) ? sh[t - off] : 0;
        __syncthreads();
        sh[t] += add;
        __syncthreads();
    }
    g_bsum[t] = sh[t] - v;
}
__global__ void k_scan3() {
    int i = blockIdx.x * blockDim.x + threadIdx.x;
    if (i < NN) {
        int rs = g_row[i] + g_bsum[i >> 8];
        g_row[i] = rs;
        g_fill[i] = rs;
    }
}
__global__ void k_fill(const int* __restrict__ src, const int* __restrict__ dst) {
    int e = blockIdx.x * blockDim.x + threadIdx.x;
    if (e < NE) {
        int d = dst[e];
        int p = atomicAdd(&g_fill[d], 1);
        g_csr[p] = src[e];
    }
}

// ---------------- weight prep ----------------
__global__ void k_prepw(const float* __restrict__ W1_0, const float* __restrict__ W1,
                        const float* __restrict__ W2, const float* __restrict__ Wr1) {
    int img = blockIdx.y;
    int idx = blockIdx.x * 256 + threadIdx.x;
    if (idx >= BIMG) return;
    int n = idx / 136;
    int k = idx % 136;
    int Kreal = (img == 0) ? 16 : 128;
    const float* W = (img == 0) ? W1_0
                   : (img <= 7) ? (W1 + (size_t)(img - 1) * 16384)
                   : (img <= 15) ? (W2 + (size_t)(img - 8) * 16384)
                   : Wr1;
    float w = (k < Kreal) ? W[(size_t)k * 128 + n] : 0.f;
    __nv_bfloat16 hi = __float2bfloat16_rn(w);
    __nv_bfloat16 lo = __float2bfloat16_rn(w - __bfloat162float(hi));
    g_Bh[(size_t)img * BIMG + idx] = hi;
    g_Bl[(size_t)img * BIMG + idx] = lo;
}

// ---------------- aggregation (R6/R12 frozen shape) ----------------
__global__ void k_agg(const __half* __restrict__ hin, float* __restrict__ zout,
                      const float* __restrict__ eps, int layer) {
    int gt = blockIdx.x * blockDim.x + threadIdx.x;
    int node = gt >> 5;
    int lane = gt & 31;
    if (node >= NN) return;
    float e1 = 1.f + __ldg(&eps[layer]);
    const uint2* h2 = (const uint2*)hin;
    int start = g_row[node];
    int d = g_deg[node];

    uint2 ua = h2[(size_t)node * 32 + lane];
    float2 a0 = __half22float2(*(__half2*)&ua.x);
    float2 a1 = __half22float2(*(__half2*)&ua.y);
    float4 acc0 = make_float4(a0.x * e1, a0.y * e1, a1.x * e1, a1.y * e1);
    float4 acc1 = make_float4(0.f, 0.f, 0.f, 0.f);
    int j = 0;
    for (; j + 2 <= d; j += 2) {
        int s0 = __ldg(&g_csr[start + j]);
        int s1 = __ldg(&g_csr[start + j + 1]);
        uint2 u0 = h2[(size_t)s0 * 32 + lane];
        uint2 u1 = h2[(size_t)s1 * 32 + lane];
        float2 v00 = __half22float2(*(__half2*)&u0.x);
        float2 v01 = __half22float2(*(__half2*)&u0.y);
        float2 v10 = __half22float2(*(__half2*)&u1.x);
        float2 v11 = __half22float2(*(__half2*)&u1.y);
        acc0.x += v00.x; acc0.y += v00.y; acc0.z += v01.x; acc0.w += v01.y;
        acc1.x += v10.x; acc1.y += v10.y; acc1.z += v11.x; acc1.w += v11.y;
    }
    if (j < d) {
        int s = __ldg(&g_csr[start + j]);
        uint2 u = h2[(size_t)s * 32 + lane];
        float2 v0 = __half22float2(*(__half2*)&u.x);
        float2 v1 = __half22float2(*(__half2*)&u.y);
        acc0.x += v0.x; acc0.y += v0.y; acc0.z += v1.x; acc0.w += v1.y;
    }
    ((float4*)zout)[(size_t)node * 32 + lane] =
        make_float4(acc0.x + acc1.x, acc0.y + acc1.y, acc0.z + acc1.z, acc0.w + acc1.w);
}

__global__ void k_agg0(const float* __restrict__ x, float* __restrict__ z0,
                       const float* __restrict__ eps) {
    int t = blockIdx.x * blockDim.x + threadIdx.x;
    if (t >= NN * 4) return;
    int n = t >> 2;
    float e1 = 1.f + __ldg(&eps[0]);
    const float4* x4 = (const float4*)x;
    float4 a = x4[t];
    float4 acc = make_float4(a.x * e1, a.y * e1, a.z * e1, a.w * e1);
    int start = g_row[n];
    int d = g_deg[n];
    int q = t & 3;
    for (int j = 0; j < d; j++) {
        int s = __ldg(&g_csr[start + j]);
        float4 v = x4[(size_t)s * 4 + q];
        acc.x += v.x; acc.y += v.y; acc.z += v.z; acc.w += v.w;
    }
    ((float4*)z0)[t] = acc;
}

// ---------------- post: reads fp16 z; h(fp16) = relu(bn(z)); skip modes ----------------
// skipmode 0: h only; 1: h + skip=v; 2: h + skip+=v; 3: skip+=v only (no h store)
__global__ void k_post(const __half* __restrict__ y, __half* __restrict__ h, int skipmode,
                       const float* __restrict__ gamma, const float* __restrict__ beta,
                       int slot) {
    __shared__ float ssc[128], ssh[128];
    int tid = threadIdx.x;
    if (tid < 128) {
        float sc, sh;
        bn_coef(slot, tid, gamma, beta, sc, sh);
        ssc[tid] = sc;
        ssh[tid] = sh;
    }
    __syncthreads();
    int i = blockIdx.x * blockDim.x + tid;
    if (i >= NN * 32) return;
    int c4 = (i & 31) * 4;
    float4 sc = *(float4*)(ssc + c4);
    float4 sh = *(float4*)(ssh + c4);
    uint2 u = ((const uint2*)y)[i];
    float2 za = __half22float2(*(__half2*)&u.x);
    float2 zb = __half22float2(*(__half2*)&u.y);
    float4 v;
    v.x = fmaxf(fmaf(za.x, sc.x, sh.x), 0.f);
    v.y = fmaxf(fmaf(za.y, sc.y, sh.y), 0.f);
    v.z = fmaxf(fmaf(zb.x, sc.z, sh.z), 0.f);
    v.w = fmaxf(fmaf(zb.y, sc.w, sh.w), 0.f);
    if (skipmode != 3) {
        __half2 p0 = __floats2half2_rn(v.x, v.y);
        __half2 p1 = __floats2half2_rn(v.z, v.w);
        ((uint2*)h)[i] = make_uint2(*(uint32_t*)&p0, *(uint32_t*)&p1);
    }
    if (skipmode == 1) {
        ((float4*)g_skip)[i] = v;
    } else if (skipmode == 2 || skipmode == 3) {
        float4 s = ((float4*)g_skip)[i];
        s.x += v.x; s.y += v.y; s.z += v.z; s.w += v.w;
        ((float4*)g_skip)[i] = s;
    }
}

// ---------------- mma.sync bf16x3 GEMM, persistent, M-tile=64, occupancy 2 ----------------
// MODE 0: identity; 1: relu(A*sc+sh) from slotIn; 2: A*0.25.  OUTH: C stored fp16.
#define SM_AH 0
#define SM_AL 17408
#define SM_BH 34816
#define SM_BL 69632
#define SM_BI 104448
#define SM_RD 104960
#define SM_SC 105984
#define SM_SH 106496
#define SMEM_MG 107008

template<int MODE, int KR, int OUTH>
__global__ void __launch_bounds__(256, 2)
k_mgemm(const float* __restrict__ A, const __nv_bfloat16* __restrict__ Bh,
        const __nv_bfloat16* __restrict__ Bl, const float* __restrict__ bias,
        void* __restrict__ Cv, const float* __restrict__ gamma,
        const float* __restrict__ beta, int slotIn, int slotOut) {
    extern __shared__ char smem[];
    uint32_t sb = smem_u32(smem);
    float* fs = (float*)smem;
    float* Cf = (float*)Cv;
    __half* Ch = (__half*)Cv;
    const int tid = threadIdx.x, lane = tid & 31, wid = tid >> 5;
    const int wm = wid >> 2, wn = wid & 3;   // wm in {0,1}: 32 rows each

    for (int i = tid * 16; i < 34816; i += 4096) {
        *(uint4*)(smem + SM_BH + i) = *(const uint4*)((const char*)Bh + i);
        *(uint4*)(smem + SM_BL + i) = *(const uint4*)((const char*)Bl + i);
    }
    if (tid < 128) {
        fs[(SM_BI >> 2) + tid] = __ldg(&bias[tid]);
        fs[(SM_RD >> 2) + tid] = 0.f;
        fs[(SM_RD >> 2) + 128 + tid] = 0.f;
        if (MODE == 1) {
            float sc, sh;
            bn_coef(slotIn, tid, gamma, beta, sc, sh);
            fs[(SM_SC >> 2) + tid] = sc;
            fs[(SM_SH >> 2) + tid] = sh;
        }
    }

    const uint32_t a_row = (lane & 7) + ((lane >> 3) & 1) * 8;
    const uint32_t a_kb  = (lane >> 4) * 16;
    const uint32_t b_n   = (lane & 7) + ((lane >> 4) & 1) * 8;
    const uint32_t b_kb  = ((lane >> 3) & 1) * 16;

    constexpr int F4R = KR / 4;
    constexpr int NIT = (64 * F4R) / 256;   // 8 for KR=128, 1 for KR=16

    float4 v[NIT];
    {
        int mb = blockIdx.x * 64;
        #pragma unroll
        for (int i = 0; i < NIT; i++) {
            int idx = tid + i * 256;
            int row = idx / F4R;
            int c = (idx % F4R) * 4;
            v[i] = make_float4(0.f, 0.f, 0.f, 0.f);
            if (mb + row < NN) v[i] = f4ld(A + (size_t)(mb + row) * KR + c);
        }
    }

    for (int tile = blockIdx.x; tile < NT64; tile += gridDim.x) {
        int mb = tile * 64;
        __syncthreads();

        #pragma unroll
        for (int i = 0; i < NIT; i++) {
            int idx = tid + i * 256;
            int row = idx / F4R;
            int c = (idx % F4R) * 4;
            float4 w = v[i];
            if (MODE == 1) {
                float4 sc = *(float4*)(fs + (SM_SC >> 2) + c);
                float4 sh = *(float4*)(fs + (SM_SH >> 2) + c);
                w.x = fmaxf(fmaf(w.x, sc.x, sh.x), 0.f);
                w.y = fmaxf(fmaf(w.y, sc.y, sh.y), 0.f);
                w.z = fmaxf(fmaf(w.z, sc.z, sh.z), 0.f);
                w.w = fmaxf(fmaf(w.w, sc.w, sh.w), 0.f);
            } else if (MODE == 2) {
                w.x *= 0.25f; w.y *= 0.25f; w.z *= 0.25f; w.w *= 0.25f;
            }
            if (MODE == 1 && mb + row >= NN) w = make_float4(0.f, 0.f, 0.f, 0.f);
            __nv_bfloat16 hx = __float2bfloat16_rn(w.x);
            __nv_bfloat16 hy = __float2bfloat16_rn(w.y);
            __nv_bfloat16 hz = __float2bfloat16_rn(w.z);
            __nv_bfloat16 hw = __float2bfloat16_rn(w.w);
            __nv_bfloat16 lx = __float2bfloat16_rn(w.x - __bfloat162float(hx));
            __nv_bfloat16 ly = __float2bfloat16_rn(w.y - __bfloat162float(hy));
            __nv_bfloat16 lz = __float2bfloat16_rn(w.z - __bfloat162float(hz));
            __nv_bfloat16 lw = __float2bfloat16_rn(w.w - __bfloat162float(hw));
            uint32_t off = (uint32_t)row * 272u + (uint32_t)c * 2u;
            *(uint2*)(smem + SM_AH + off) = make_uint2(pk(hx, hy), pk(hz, hw));
            *(uint2*)(smem + SM_AL + off) = make_uint2(pk(lx, ly), pk(lz, lw));
        }
        __syncthreads();

        int nt = tile + gridDim.x;
        if (nt < NT64) {
            int nmb = nt * 64;
            #pragma unroll
            for (int i = 0; i < NIT; i++) {
                int idx = tid + i * 256;
                int row = idx / F4R;
                int c = (idx % F4R) * 4;
                float4 nv = make_float4(0.f, 0.f, 0.f, 0.f);
                if (nmb + row < NN) nv = f4ld(A + (size_t)(nmb + row) * KR + c);
                v[i] = nv;
            }
        }

        float acc[2][4][4];
        #pragma unroll
        for (int mi = 0; mi < 2; mi++)
            #pragma unroll
            for (int ni = 0; ni < 4; ni++)
                #pragma unroll
                for (int r = 0; r < 4; r++) acc[mi][ni][r] = 0.f;

        #pragma unroll
        for (int ks = 0; ks < KR / 16; ks++) {
            uint32_t kb = ks * 32;
            uint32_t ah[2][4], al[2][4], bh2[2][4], bl2[2][4];
            #pragma unroll
            for (int mi = 0; mi < 2; mi++) {
                uint32_t addr = sb + SM_AH + (wm * 32 + mi * 16 + a_row) * 272 + a_kb + kb;
                LDM4(ah[mi], addr);
                LDM4(al[mi], addr + 17408);
            }
            #pragma unroll
            for (int g = 0; g < 2; g++) {
                uint32_t addr = sb + SM_BH + (wn * 32 + g * 16 + b_n) * 272 + b_kb + kb;
                LDM4(bh2[g], addr);
                LDM4(bl2[g], addr + 34816);
            }
            #pragma unroll
            for (int mi = 0; mi < 2; mi++)
                #pragma unroll
                for (int ni = 0; ni < 4; ni++) {
                    uint32_t b0h = bh2[ni >> 1][(ni & 1) * 2];
                    uint32_t b1h = bh2[ni >> 1][(ni & 1) * 2 + 1];
                    uint32_t b0l = bl2[ni >> 1][(ni & 1) * 2];
                    uint32_t b1l = bl2[ni >> 1][(ni & 1) * 2 + 1];
                    MMA16(acc[mi][ni], ah[mi], b0h, b1h);
                    MMA16(acc[mi][ni], al[mi], b0h, b1h);
                    MMA16(acc[mi][ni], ah[mi], b0l, b1l);
                }
        }

        float s0[4], s1[4], q0[4], q1[4];
        #pragma unroll
        for (int ni = 0; ni < 4; ni++) { s0[ni] = s1[ni] = q0[ni] = q1[ni] = 0.f; }
        #pragma unroll
        for (int mi = 0; mi < 2; mi++) {
            int row0 = mb + wm * 32 + mi * 16 + (lane >> 2);
            int row1 = row0 + 8;
            #pragma unroll
            for (int ni = 0; ni < 4; ni++) {
                int col = wn * 32 + ni * 8 + (lane & 3) * 2;
                float bb0 = fs[(SM_BI >> 2) + col];
                float bb1 = fs[(SM_BI >> 2) + col + 1];
                float v0 = acc[mi][ni][0] + bb0;
                float v1 = acc[mi][ni][1] + bb1;
                float v2 = acc[mi][ni][2] + bb0;
                float v3 = acc[mi][ni][3] + bb1;
                if (row0 < NN) {
                    if (OUTH) {
                        __half2 hv = __floats2half2_rn(v0, v1);
                        *(uint32_t*)(Ch + (size_t)row0 * 128 + col) = *(uint32_t*)&hv;
                    } else {
                        *(float2*)(Cf + (size_t)row0 * 128 + col) = make_float2(v0, v1);
                    }
                    s0[ni] += v0; s1[ni] += v1; q0[ni] += v0 * v0; q1[ni] += v1 * v1;
                }
                if (row1 < NN) {
                    if (OUTH) {
                        __half2 hv = __floats2half2_rn(v2, v3);
                        *(uint32_t*)(Ch + (size_t)row1 * 128 + col) = *(uint32_t*)&hv;
                    } else {
                        *(float2*)(Cf + (size_t)row1 * 128 + col) = make_float2(v2, v3);
                    }
                    s0[ni] += v2; s1[ni] += v3; q0[ni] += v2 * v2; q1[ni] += v3 * v3;
                }
            }
        }
        #pragma unroll
        for (int ni = 0; ni < 4; ni++) {
            #pragma unroll
            for (int off = 4; off < 32; off <<= 1) {
                s0[ni] += __shfl_xor_sync(0xffffffffu, s0[ni], off);
                s1[ni] += __shfl_xor_sync(0xffffffffu, s1[ni], off);
                q0[ni] += __shfl_xor_sync(0xffffffffu, q0[ni], off);
                q1[ni] += __shfl_xor_sync(0xffffffffu, q1[ni], off);
            }
            if (lane < 4) {
                int col = wn * 32 + ni * 8 + lane * 2;
                atomicAdd(&fs[(SM_RD >> 2) + col], s0[ni]);
                atomicAdd(&fs[(SM_RD >> 2) + col + 1], s1[ni]);
                atomicAdd(&fs[(SM_RD >> 2) + 128 + col], q0[ni]);
                atomicAdd(&fs[(SM_RD >> 2) + 128 + col + 1], q1[ni]);
            }
        }
    }
    __syncthreads();
    if (tid < 128) {
        atomicAdd(&g_st[slotOut * 256 + tid], fs[(SM_RD >> 2) + tid]);
        atomicAdd(&g_st[slotOut * 256 + 128 + tid], fs[(SM_RD >> 2) + 128 + tid]);
    }
}

// ---------------- final ----------------
__global__ void k_final(const float* __restrict__ y, const float* __restrict__ Wr2,
                        const float* __restrict__ br2, const float* __restrict__ gamma,
                        const float* __restrict__ beta, float* __restrict__ out) {
    __shared__ float w[128], ssc[128], ssh[128];
    int tid = threadIdx.x;
    if (tid < 128) {
        w[tid] = Wr2[tid];
        float sc, sh;
        bn_coef(16, tid, gamma, beta, sc, sh);
        ssc[tid] = sc;
        ssh[tid] = sh;
    }
    __syncthreads();
    int gt = blockIdx.x * blockDim.x + tid;
    int n = gt >> 5;
    int lane = gt & 31;
    if (n >= NN) return;
    float4 v = ((const float4*)y)[(size_t)n * 32 + lane];
    float4 sc = *(float4*)(ssc + lane * 4);
    float4 sh = *(float4*)(ssh + lane * 4);
    float d = fmaxf(fmaf(v.x, sc.x, sh.x), 0.f) * w[lane * 4 + 0]
            + fmaxf(fmaf(v.y, sc.y, sh.y), 0.f) * w[lane * 4 + 1]
            + fmaxf(fmaf(v.z, sc.z, sh.z), 0.f) * w[lane * 4 + 2]
            + fmaxf(fmaf(v.w, sc.w, sh.w), 0.f) * w[lane * 4 + 3];
    #pragma unroll
    for (int off = 16; off > 0; off >>= 1)
        d += __shfl_xor_sync(0xffffffffu, d, off);
    if (lane == 0) out[n] = 1.f / (1.f + expf(-(d + __ldg(br2))));
}

// ---------------- host ----------------
extern "C" void kernel_launch(void* const* d_in, const int* in_sizes, int n_in,
                              void* d_out, int out_size) {
    const float* x     = (const float*)d_in[0];
    const int*   ei    = (const int*)d_in[1];
    const float* eps   = (const float*)d_in[2];
    const float* W1_0  = (const float*)d_in[3];
    const float* b1_0  = (const float*)d_in[4];
    const float* W1    = (const float*)d_in[5];
    const float* b1    = (const float*)d_in[6];
    const float* g_in  = (const float*)d_in[7];
    const float* be_in = (const float*)d_in[8];
    const float* W2    = (const float*)d_in[9];
    const float* b2    = (const float*)d_in[10];
    const float* g_out = (const float*)d_in[11];
    const float* be_out= (const float*)d_in[12];
    const float* Wr1   = (const float*)d_in[13];
    const float* br1   = (const float*)d_in[14];
    const float* gr    = (const float*)d_in[15];
    const float* ber   = (const float*)d_in[16];
    const float* Wr2   = (const float*)d_in[17];
    const float* br2   = (const float*)d_in[18];
    const int* srcp = ei;
    const int* dstp = ei + NE;

    float *y1, *skip, *za, *z0;
    __half *hh, *zh;
    __nv_bfloat16 *bh, *bl;
    cudaGetSymbolAddress((void**)&hh, g_hh);
    cudaGetSymbolAddress((void**)&zh, g_zh);
    cudaGetSymbolAddress((void**)&y1, g_y1);
    cudaGetSymbolAddress((void**)&skip, g_skip);
    cudaGetSymbolAddress((void**)&za, g_za);
    cudaGetSymbolAddress((void**)&z0, g_z0);
    cudaGetSymbolAddress((void**)&bh, g_Bh);
    cudaGetSymbolAddress((void**)&bl, g_Bl);

    cudaFuncSetAttribute(k_mgemm<0,16,0>,  cudaFuncAttributeMaxDynamicSharedMemorySize, SMEM_MG);
    cudaFuncSetAttribute(k_mgemm<0,128,0>, cudaFuncAttributeMaxDynamicSharedMemorySize, SMEM_MG);
    cudaFuncSetAttribute(k_mgemm<1,128,1>, cudaFuncAttributeMaxDynamicSharedMemorySize, SMEM_MG);
    cudaFuncSetAttribute(k_mgemm<2,128,0>, cudaFuncAttributeMaxDynamicSharedMemorySize, SMEM_MG);

    const int GGRID = 296;   // 148 SMs x occupancy 2

    k_zero<<<(NN + 255) / 256, 256>>>();
    k_hist<<<(NE + 255) / 256, 256>>>(dstp);
    k_scan1<<<NB_SCAN, 256>>>();
    k_scan2<<<1, 512>>>();
    k_scan3<<<NB_SCAN, 256>>>();
    k_fill<<<(NE + 255) / 256, 256>>>(srcp, dstp);
    {
        dim3 g((BIMG + 255) / 256, 17);
        k_prepw<<<g, 256>>>(W1_0, W1, W2, Wr1);
    }

    for (int i = 0; i < NL; i++) {
        if (i == 0)
            k_agg0<<<(NN * 4 + 255) / 256, 256>>>(x, z0, eps);
        else
            k_agg<<<(NN * 32 + 255) / 256, 256>>>(hh, za, eps, i);

        const float* ba = (i == 0) ? b1_0 : (b1 + (size_t)(i - 1) * HIDD);
        int imgA = (i == 0) ? 0 : i;
        if (i == 0)
            k_mgemm<0,16,0><<<GGRID, 256, SMEM_MG>>>(z0, bh, bl, ba, y1,
                                                     (const float*)0, (const float*)0, 0, 0);
        else
            k_mgemm<0,128,0><<<GGRID, 256, SMEM_MG>>>(za, bh + (size_t)imgA * BIMG,
                                                      bl + (size_t)imgA * BIMG, ba, y1,
                                                      (const float*)0, (const float*)0, 0, i);

        int imgB = 8 + i;
        k_mgemm<1,128,1><<<GGRID, 256, SMEM_MG>>>(y1, bh + (size_t)imgB * BIMG,
                                                  bl + (size_t)imgB * BIMG,
                                                  b2 + (size_t)i * HIDD, zh,
                                                  g_in + (size_t)i * HIDD,
                                                  be_in + (size_t)i * HIDD, i, 8 + i);

        // skipmode: layer 1 -> store, layers 3/5 -> add, layer 7 -> add only (h unused after)
        int sm = (i % 2 == 1) ? ((i == 1) ? 1 : ((i == 7) ? 3 : 2)) : 0;
        k_post<<<(NN * 32 + 255) / 256, 256>>>(zh, hh, sm,
                                               g_out + (size_t)i * HIDD,
                                               be_out + (size_t)i * HIDD, 8 + i);
    }

    // regressor
    k_mgemm<2,128,0><<<GGRID, 256, SMEM_MG>>>(skip, bh + (size_t)16 * BIMG,
                                              bl + (size_t)16 * BIMG, br1, y1,
                                              (const float*)0, (const float*)0, 0, 16);
    k_final<<<(NN * 32 + 255) / 256, 256>>>(y1, Wr2, br2, gr, ber, (float*)d_out);
}

// round 17
// speedup vs baseline: 1.1572x; 1.0006x over previous
#include <cuda_runtime.h>
#include <cuda_bf16.h>
#include <cuda_fp16.h>
#include <math.h>
#include <stdint.h>

#define NN   100000
#define NE   1600000
#define INF  16
#define HIDD 128
#define NL   8
#define NB_SCAN 391    /* ceil(NN/256) */
#define NT64  1563     /* ceil(NN/64) */

// ---------------- device scratch ----------------
__device__ __align__(16) __half g_hh[NN * HIDD];   // post-activation h (fp16)
__device__ __align__(16) __half g_zh[NN * HIDD];   // raw GEMM<1> output (fp16)
__device__ __align__(16) float g_y1[NN * HIDD];
__device__ __align__(16) float g_skip[NN * HIDD];
__device__ __align__(16) float g_za[NN * HIDD];    // agg output
__device__ __align__(16) float g_z0[NN * INF];
__device__ int   g_deg[NN];
__device__ int   g_row[NN];
__device__ int   g_fill[NN];
__device__ int   g_csr[NE];
__device__ int   g_bsum[512];
// BN stats slots: i (0..7)=inner BN layer i, 8+i=outer BN layer i, 16=regressor
__device__ __align__(16) float g_st[17 * 256];
#define BIMG 17408
__device__ __align__(16) __nv_bfloat16 g_Bh[17 * BIMG];
__device__ __align__(16) __nv_bfloat16 g_Bl[17 * BIMG];

__device__ __forceinline__ float4 f4ld(const float* p) { return *(const float4*)p; }

__device__ __forceinline__ uint32_t smem_u32(const void* p) {
    uint32_t a;
    asm("{ .reg .u64 t; cvta.to.shared.u64 t, %1; cvt.u32.u64 %0, t; }" : "=r"(a) : "l"(p));
    return a;
}
__device__ __forceinline__ uint32_t pk(__nv_bfloat16 a, __nv_bfloat16 b) {
    __nv_bfloat162 t(a, b);
    return *(uint32_t*)&t;
}

#define LDM4(r, addr) \
    asm volatile("ldmatrix.sync.aligned.m8n8.x4.shared.b16 {%0,%1,%2,%3}, [%4];" \
        : "=r"((r)[0]), "=r"((r)[1]), "=r"((r)[2]), "=r"((r)[3]) : "r"(addr))

#define MMA16(acc, a, b0, b1) \
    asm volatile("mma.sync.aligned.m16n8k16.row.col.f32.bf16.bf16.f32 " \
        "{%0,%1,%2,%3}, {%4,%5,%6,%7}, {%8,%9}, {%0,%1,%2,%3};" \
        : "+f"((acc)[0]), "+f"((acc)[1]), "+f"((acc)[2]), "+f"((acc)[3]) \
        : "r"((a)[0]), "r"((a)[1]), "r"((a)[2]), "r"((a)[3]), "r"(b0), "r"(b1))

__device__ __forceinline__ void bn_coef(int slot, int t, const float* gamma,
                                        const float* beta, float& sc, float& sh) {
    float su = g_st[slot * 256 + t];
    float sq = g_st[slot * 256 + 128 + t];
    float mean = su * (1.f / NN);
    float var = sq * (1.f / NN) - mean * mean;
    float rstd = rsqrtf(fmaxf(var, 0.f) + 1e-5f);
    sc = __ldg(&gamma[t]) * rstd;
    sh = __ldg(&beta[t]) - mean * sc;
}

// ---------------- weight prep + scratch zeroing (fused; must run FIRST) ----------------
__global__ void k_prepw(const float* __restrict__ W1_0, const float* __restrict__ W1,
                        const float* __restrict__ W2, const float* __restrict__ Wr1) {
    int img = blockIdx.y;
    int idx = blockIdx.x * 256 + threadIdx.x;
    // fused zeroing using the whole 2-D grid (68*17*256 = 295936 threads)
    int lin = (blockIdx.y * gridDim.x + blockIdx.x) * 256 + threadIdx.x;
    if (lin < NN) g_deg[lin] = 0;
    if (lin < 17 * 256) g_st[lin] = 0.f;
    if (idx >= BIMG) return;
    int n = idx / 136;
    int k = idx % 136;
    int Kreal = (img == 0) ? 16 : 128;
    const float* W = (img == 0) ? W1_0
                   : (img <= 7) ? (W1 + (size_t)(img - 1) * 16384)
                   : (img <= 15) ? (W2 + (size_t)(img - 8) * 16384)
                   : Wr1;
    float w = (k < Kreal) ? W[(size_t)k * 128 + n] : 0.f;
    __nv_bfloat16 hi = __float2bfloat16_rn(w);
    __nv_bfloat16 lo = __float2bfloat16_rn(w - __bfloat162float(hi));
    g_Bh[(size_t)img * BIMG + idx] = hi;
    g_Bl[(size_t)img * BIMG + idx] = lo;
}

// ---------------- CSR build ----------------
__global__ void k_hist(const int* __restrict__ dst) {
    int e = blockIdx.x * blockDim.x + threadIdx.x;
    if (e < NE) atomicAdd(&g_deg[dst[e]], 1);
}
__global__ void k_scan1() {
    __shared__ int sh[256];
    int t = threadIdx.x;
    int i = blockIdx.x * 256 + t;
    int v = (i < NN) ? g_deg[i] : 0;
    sh[t] = v;
    __syncthreads();
    #pragma unroll
    for (int off = 1; off < 256; off <<= 1) {
        int add = (t >= off) ? sh[t - off] : 0;
        __syncthreads();
        sh[t] += add;
        __syncthreads();
    }
    if (i < NN) g_row[i] = sh[t] - v;
    if (t == 255) g_bsum[blockIdx.x] = sh[255];
}
__global__ void k_scan2() {
    __shared__ int sh[512];
    int t = threadIdx.x;
    int v = (t < NB_SCAN) ? g_bsum[t] : 0;
    sh[t] = v;
    __syncthreads();
    #pragma unroll
    for (int off = 1; off < 512; off <<= 1) {
        int add = (t >= off) ? sh[t - off] : 0;
        __syncthreads();
        sh[t] += add;
        __syncthreads();
    }
    g_bsum[t] = sh[t] - v;
}
__global__ void k_scan3() {
    int i = blockIdx.x * blockDim.x + threadIdx.x;
    if (i < NN) {
        int rs = g_row[i] + g_bsum[i >> 8];
        g_row[i] = rs;
        g_fill[i] = rs;
    }
}
__global__ void k_fill(const int* __restrict__ src, const int* __restrict__ dst) {
    int e = blockIdx.x * blockDim.x + threadIdx.x;
    if (e < NE) {
        int d = dst[e];
        int p = atomicAdd(&g_fill[d], 1);
        g_csr[p] = src[e];
    }
}

// ---------------- aggregation (R6/R12 frozen shape) ----------------
__global__ void k_agg(const __half* __restrict__ hin, float* __restrict__ zout,
                      const float* __restrict__ eps, int layer) {
    int gt = blockIdx.x * blockDim.x + threadIdx.x;
    int node = gt >> 5;
    int lane = gt & 31;
    if (node >= NN) return;
    float e1 = 1.f + __ldg(&eps[layer]);
    const uint2* h2 = (const uint2*)hin;
    int start = g_row[node];
    int d = g_deg[node];

    uint2 ua = h2[(size_t)node * 32 + lane];
    float2 a0 = __half22float2(*(__half2*)&ua.x);
    float2 a1 = __half22float2(*(__half2*)&ua.y);
    float4 acc0 = make_float4(a0.x * e1, a0.y * e1, a1.x * e1, a1.y * e1);
    float4 acc1 = make_float4(0.f, 0.f, 0.f, 0.f);
    int j = 0;
    for (; j + 2 <= d; j += 2) {
        int s0 = __ldg(&g_csr[start + j]);
        int s1 = __ldg(&g_csr[start + j + 1]);
        uint2 u0 = h2[(size_t)s0 * 32 + lane];
        uint2 u1 = h2[(size_t)s1 * 32 + lane];
        float2 v00 = __half22float2(*(__half2*)&u0.x);
        float2 v01 = __half22float2(*(__half2*)&u0.y);
        float2 v10 = __half22float2(*(__half2*)&u1.x);
        float2 v11 = __half22float2(*(__half2*)&u1.y);
        acc0.x += v00.x; acc0.y += v00.y; acc0.z += v01.x; acc0.w += v01.y;
        acc1.x += v10.x; acc1.y += v10.y; acc1.z += v11.x; acc1.w += v11.y;
    }
    if (j < d) {
        int s = __ldg(&g_csr[start + j]);
        uint2 u = h2[(size_t)s * 32 + lane];
        float2 v0 = __half22float2(*(__half2*)&u.x);
        float2 v1 = __half22float2(*(__half2*)&u.y);
        acc0.x += v0.x; acc0.y += v0.y; acc0.z += v1.x; acc0.w += v1.y;
    }
    ((float4*)zout)[(size_t)node * 32 + lane] =
        make_float4(acc0.x + acc1.x, acc0.y + acc1.y, acc0.z + acc1.z, acc0.w + acc1.w);
}

__global__ void k_agg0(const float* __restrict__ x, float* __restrict__ z0,
                       const float* __restrict__ eps) {
    int t = blockIdx.x * blockDim.x + threadIdx.x;
    if (t >= NN * 4) return;
    int n = t >> 2;
    float e1 = 1.f + __ldg(&eps[0]);
    const float4* x4 = (const float4*)x;
    float4 a = x4[t];
    float4 acc = make_float4(a.x * e1, a.y * e1, a.z * e1, a.w * e1);
    int start = g_row[n];
    int d = g_deg[n];
    int q = t & 3;
    for (int j = 0; j < d; j++) {
        int s = __ldg(&g_csr[start + j]);
        float4 v = x4[(size_t)s * 4 + q];
        acc.x += v.x; acc.y += v.y; acc.z += v.z; acc.w += v.w;
    }
    ((float4*)z0)[t] = acc;
}

// ---------------- post: reads fp16 z; h(fp16) = relu(bn(z)); skip modes ----------------
// skipmode 0: h only; 1: h + skip=v; 2: h + skip+=v; 3: skip+=v only (no h store)
__global__ void k_post(const __half* __restrict__ y, __half* __restrict__ h, int skipmode,
                       const float* __restrict__ gamma, const float* __restrict__ beta,
                       int slot) {
    __shared__ float ssc[128], ssh[128];
    int tid = threadIdx.x;
    if (tid < 128) {
        float sc, sh;
        bn_coef(slot, tid, gamma, beta, sc, sh);
        ssc[tid] = sc;
        ssh[tid] = sh;
    }
    __syncthreads();
    int i = blockIdx.x * blockDim.x + tid;
    if (i >= NN * 32) return;
    int c4 = (i & 31) * 4;
    float4 sc = *(float4*)(ssc + c4);
    float4 sh = *(float4*)(ssh + c4);
    uint2 u = ((const uint2*)y)[i];
    float2 za = __half22float2(*(__half2*)&u.x);
    float2 zb = __half22float2(*(__half2*)&u.y);
    float4 v;
    v.x = fmaxf(fmaf(za.x, sc.x, sh.x), 0.f);
    v.y = fmaxf(fmaf(za.y, sc.y, sh.y), 0.f);
    v.z = fmaxf(fmaf(zb.x, sc.z, sh.z), 0.f);
    v.w = fmaxf(fmaf(zb.y, sc.w, sh.w), 0.f);
    if (skipmode != 3) {
        __half2 p0 = __floats2half2_rn(v.x, v.y);
        __half2 p1 = __floats2half2_rn(v.z, v.w);
        ((uint2*)h)[i] = make_uint2(*(uint32_t*)&p0, *(uint32_t*)&p1);
    }
    if (skipmode == 1) {
        ((float4*)g_skip)[i] = v;
    } else if (skipmode == 2 || skipmode == 3) {
        float4 s = ((float4*)g_skip)[i];
        s.x += v.x; s.y += v.y; s.z += v.z; s.w += v.w;
        ((float4*)g_skip)[i] = s;
    }
}

// ---------------- mma.sync bf16x3 GEMM, persistent, M-tile=64, occupancy 2 ----------------
// MODE 0: identity; 1: relu(A*sc+sh) from slotIn; 2: A*0.25.  OUTH: C stored fp16.
#define SM_AH 0
#define SM_AL 17408
#define SM_BH 34816
#define SM_BL 69632
#define SM_BI 104448
#define SM_RD 104960
#define SM_SC 105984
#define SM_SH 106496
#define SMEM_MG 107008

template<int MODE, int KR, int OUTH>
__global__ void __launch_bounds__(256, 2)
k_mgemm(const float* __restrict__ A, const __nv_bfloat16* __restrict__ Bh,
        const __nv_bfloat16* __restrict__ Bl, const float* __restrict__ bias,
        void* __restrict__ Cv, const float* __restrict__ gamma,
        const float* __restrict__ beta, int slotIn, int slotOut) {
    extern __shared__ char smem[];
    uint32_t sb = smem_u32(smem);
    float* fs = (float*)smem;
    float* Cf = (float*)Cv;
    __half* Ch = (__half*)Cv;
    const int tid = threadIdx.x, lane = tid & 31, wid = tid >> 5;
    const int wm = wid >> 2, wn = wid & 3;   // wm in {0,1}: 32 rows each

    for (int i = tid * 16; i < 34816; i += 4096) {
        *(uint4*)(smem + SM_BH + i) = *(const uint4*)((const char*)Bh + i);
        *(uint4*)(smem + SM_BL + i) = *(const uint4*)((const char*)Bl + i);
    }
    if (tid < 128) {
        fs[(SM_BI >> 2) + tid] = __ldg(&bias[tid]);
        fs[(SM_RD >> 2) + tid] = 0.f;
        fs[(SM_RD >> 2) + 128 + tid] = 0.f;
        if (MODE == 1) {
            float sc, sh;
            bn_coef(slotIn, tid, gamma, beta, sc, sh);
            fs[(SM_SC >> 2) + tid] = sc;
            fs[(SM_SH >> 2) + tid] = sh;
        }
    }

    const uint32_t a_row = (lane & 7) + ((lane >> 3) & 1) * 8;
    const uint32_t a_kb  = (lane >> 4) * 16;
    const uint32_t b_n   = (lane & 7) + ((lane >> 4) & 1) * 8;
    const uint32_t b_kb  = ((lane >> 3) & 1) * 16;

    constexpr int F4R = KR / 4;
    constexpr int NIT = (64 * F4R) / 256;   // 8 for KR=128, 1 for KR=16

    float4 v[NIT];
    {
        int mb = blockIdx.x * 64;
        #pragma unroll
        for (int i = 0; i < NIT; i++) {
            int idx = tid + i * 256;
            int row = idx / F4R;
            int c = (idx % F4R) * 4;
            v[i] = make_float4(0.f, 0.f, 0.f, 0.f);
            if (mb + row < NN) v[i] = f4ld(A + (size_t)(mb + row) * KR + c);
        }
    }

    for (int tile = blockIdx.x; tile < NT64; tile += gridDim.x) {
        int mb = tile * 64;
        __syncthreads();

        #pragma unroll
        for (int i = 0; i < NIT; i++) {
            int idx = tid + i * 256;
            int row = idx / F4R;
            int c = (idx % F4R) * 4;
            float4 w = v[i];
            if (MODE == 1) {
                float4 sc = *(float4*)(fs + (SM_SC >> 2) + c);
                float4 sh = *(float4*)(fs + (SM_SH >> 2) + c);
                w.x = fmaxf(fmaf(w.x, sc.x, sh.x), 0.f);
                w.y = fmaxf(fmaf(w.y, sc.y, sh.y), 0.f);
                w.z = fmaxf(fmaf(w.z, sc.z, sh.z), 0.f);
                w.w = fmaxf(fmaf(w.w, sc.w, sh.w), 0.f);
            } else if (MODE == 2) {
                w.x *= 0.25f; w.y *= 0.25f; w.z *= 0.25f; w.w *= 0.25f;
            }
            if (MODE == 1 && mb + row >= NN) w = make_float4(0.f, 0.f, 0.f, 0.f);
            __nv_bfloat16 hx = __float2bfloat16_rn(w.x);
            __nv_bfloat16 hy = __float2bfloat16_rn(w.y);
            __nv_bfloat16 hz = __float2bfloat16_rn(w.z);
            __nv_bfloat16 hw = __float2bfloat16_rn(w.w);
            __nv_bfloat16 lx = __float2bfloat16_rn(w.x - __bfloat162float(hx));
            __nv_bfloat16 ly = __float2bfloat16_rn(w.y - __bfloat162float(hy));
            __nv_bfloat16 lz = __float2bfloat16_rn(w.z - __bfloat162float(hz));
            __nv_bfloat16 lw = __float2bfloat16_rn(w.w - __bfloat162float(hw));
            uint32_t off = (uint32_t)row * 272u + (uint32_t)c * 2u;
            *(uint2*)(smem + SM_AH + off) = make_uint2(pk(hx, hy), pk(hz, hw));
            *(uint2*)(smem + SM_AL + off) = make_uint2(pk(lx, ly), pk(lz, lw));
        }
        __syncthreads();

        int nt = tile + gridDim.x;
        if (nt < NT64) {
            int nmb = nt * 64;
            #pragma unroll
            for (int i = 0; i < NIT; i++) {
                int idx = tid + i * 256;
                int row = idx / F4R;
                int c = (idx % F4R) * 4;
                float4 nv = make_float4(0.f, 0.f, 0.f, 0.f);
                if (nmb + row < NN) nv = f4ld(A + (size_t)(nmb + row) * KR + c);
                v[i] = nv;
            }
        }

        float acc[2][4][4];
        #pragma unroll
        for (int mi = 0; mi < 2; mi++)
            #pragma unroll
            for (int ni = 0; ni < 4; ni++)
                #pragma unroll
                for (int r = 0; r < 4; r++) acc[mi][ni][r] = 0.f;

        #pragma unroll
        for (int ks = 0; ks < KR / 16; ks++) {
            uint32_t kb = ks * 32;
            uint32_t ah[2][4], al[2][4], bh2[2][4], bl2[2][4];
            #pragma unroll
            for (int mi = 0; mi < 2; mi++) {
                uint32_t addr = sb + SM_AH + (wm * 32 + mi * 16 + a_row) * 272 + a_kb + kb;
                LDM4(ah[mi], addr);
                LDM4(al[mi], addr + 17408);
            }
            #pragma unroll
            for (int g = 0; g < 2; g++) {
                uint32_t addr = sb + SM_BH + (wn * 32 + g * 16 + b_n) * 272 + b_kb + kb;
                LDM4(bh2[g], addr);
                LDM4(bl2[g], addr + 34816);
            }
            #pragma unroll
            for (int mi = 0; mi < 2; mi++)
                #pragma unroll
                for (int ni = 0; ni < 4; ni++) {
                    uint32_t b0h = bh2[ni >> 1][(ni & 1) * 2];
                    uint32_t b1h = bh2[ni >> 1][(ni & 1) * 2 + 1];
                    uint32_t b0l = bl2[ni >> 1][(ni & 1) * 2];
                    uint32_t b1l = bl2[ni >> 1][(ni & 1) * 2 + 1];
                    MMA16(acc[mi][ni], ah[mi], b0h, b1h);
                    MMA16(acc[mi][ni], al[mi], b0h, b1h);
                    MMA16(acc[mi][ni], ah[mi], b0l, b1l);
                }
        }

        float s0[4], s1[4], q0[4], q1[4];
        #pragma unroll
        for (int ni = 0; ni < 4; ni++) { s0[ni] = s1[ni] = q0[ni] = q1[ni] = 0.f; }
        #pragma unroll
        for (int mi = 0; mi < 2; mi++) {
            int row0 = mb + wm * 32 + mi * 16 + (lane >> 2);
            int row1 = row0 + 8;
            #pragma unroll
            for (int ni = 0; ni < 4; ni++) {
                int col = wn * 32 + ni * 8 + (lane & 3) * 2;
                float bb0 = fs[(SM_BI >> 2) + col];
                float bb1 = fs[(SM_BI >> 2) + col + 1];
                float v0 = acc[mi][ni][0] + bb0;
                float v1 = acc[mi][ni][1] + bb1;
                float v2 = acc[mi][ni][2] + bb0;
                float v3 = acc[mi][ni][3] + bb1;
                if (row0 < NN) {
                    if (OUTH) {
                        __half2 hv = __floats2half2_rn(v0, v1);
                        *(uint32_t*)(Ch + (size_t)row0 * 128 + col) = *(uint32_t*)&hv;
                    } else {
                        *(float2*)(Cf + (size_t)row0 * 128 + col) = make_float2(v0, v1);
                    }
                    s0[ni] += v0; s1[ni] += v1; q0[ni] += v0 * v0; q1[ni] += v1 * v1;
                }
                if (row1 < NN) {
                    if (OUTH) {
                        __half2 hv = __floats2half2_rn(v2, v3);
                        *(uint32_t*)(Ch + (size_t)row1 * 128 + col) = *(uint32_t*)&hv;
                    } else {
                        *(float2*)(Cf + (size_t)row1 * 128 + col) = make_float2(v2, v3);
                    }
                    s0[ni] += v2; s1[ni] += v3; q0[ni] += v2 * v2; q1[ni] += v3 * v3;
                }
            }
        }
        #pragma unroll
        for (int ni = 0; ni < 4; ni++) {
            #pragma unroll
            for (int off = 4; off < 32; off <<= 1) {
                s0[ni] += __shfl_xor_sync(0xffffffffu, s0[ni], off);
                s1[ni] += __shfl_xor_sync(0xffffffffu, s1[ni], off);
                q0[ni] += __shfl_xor_sync(0xffffffffu, q0[ni], off);
                q1[ni] += __shfl_xor_sync(0xffffffffu, q1[ni], off);
            }
            if (lane < 4) {
                int col = wn * 32 + ni * 8 + lane * 2;
                atomicAdd(&fs[(SM_RD >> 2) + col], s0[ni]);
                atomicAdd(&fs[(SM_RD >> 2) + col + 1], s1[ni]);
                atomicAdd(&fs[(SM_RD >> 2) + 128 + col], q0[ni]);
                atomicAdd(&fs[(SM_RD >> 2) + 128 + col + 1], q1[ni]);
            }
        }
    }
    __syncthreads();
    if (tid < 128) {
        atomicAdd(&g_st[slotOut * 256 + tid], fs[(SM_RD >> 2) + tid]);
        atomicAdd(&g_st[slotOut * 256 + 128 + tid], fs[(SM_RD >> 2) + 128 + tid]);
    }
}

// ---------------- final ----------------
__global__ void k_final(const float* __restrict__ y, const float* __restrict__ Wr2,
                        const float* __restrict__ br2, const float* __restrict__ gamma,
                        const float* __restrict__ beta, float* __restrict__ out) {
    __shared__ float w[128], ssc[128], ssh[128];
    int tid = threadIdx.x;
    if (tid < 128) {
        w[tid] = Wr2[tid];
        float sc, sh;
        bn_coef(16, tid, gamma, beta, sc, sh);
        ssc[tid] = sc;
        ssh[tid] = sh;
    }
    __syncthreads();
    int gt = blockIdx.x * blockDim.x + tid;
    int n = gt >> 5;
    int lane = gt & 31;
    if (n >= NN) return;
    float4 v = ((const float4*)y)[(size_t)n * 32 + lane];
    float4 sc = *(float4*)(ssc + lane * 4);
    float4 sh = *(float4*)(ssh + lane * 4);
    float d = fmaxf(fmaf(v.x, sc.x, sh.x), 0.f) * w[lane * 4 + 0]
            + fmaxf(fmaf(v.y, sc.y, sh.y), 0.f) * w[lane * 4 + 1]
            + fmaxf(fmaf(v.z, sc.z, sh.z), 0.f) * w[lane * 4 + 2]
            + fmaxf(fmaf(v.w, sc.w, sh.w), 0.f) * w[lane * 4 + 3];
    #pragma unroll
    for (int off = 16; off > 0; off >>= 1)
        d += __shfl_xor_sync(0xffffffffu, d, off);
    if (lane == 0) out[n] = 1.f / (1.f + expf(-(d + __ldg(br2))));
}

// ---------------- host ----------------
extern "C" void kernel_launch(void* const* d_in, const int* in_sizes, int n_in,
                              void* d_out, int out_size) {
    const float* x     = (const float*)d_in[0];
    const int*   ei    = (const int*)d_in[1];
    const float* eps   = (const float*)d_in[2];
    const float* W1_0  = (const float*)d_in[3];
    const float* b1_0  = (const float*)d_in[4];
    const float* W1    = (const float*)d_in[5];
    const float* b1    = (const float*)d_in[6];
    const float* g_in  = (const float*)d_in[7];
    const float* be_in = (const float*)d_in[8];
    const float* W2    = (const float*)d_in[9];
    const float* b2    = (const float*)d_in[10];
    const float* g_out = (const float*)d_in[11];
    const float* be_out= (const float*)d_in[12];
    const float* Wr1   = (const float*)d_in[13];
    const float* br1   = (const float*)d_in[14];
    const float* gr    = (const float*)d_in[15];
    const float* ber   = (const float*)d_in[16];
    const float* Wr2   = (const float*)d_in[17];
    const float* br2   = (const float*)d_in[18];
    const int* srcp = ei;
    const int* dstp = ei + NE;

    float *y1, *skip, *za, *z0;
    __half *hh, *zh;
    __nv_bfloat16 *bh, *bl;
    cudaGetSymbolAddress((void**)&hh, g_hh);
    cudaGetSymbolAddress((void**)&zh, g_zh);
    cudaGetSymbolAddress((void**)&y1, g_y1);
    cudaGetSymbolAddress((void**)&skip, g_skip);
    cudaGetSymbolAddress((void**)&za, g_za);
    cudaGetSymbolAddress((void**)&z0, g_z0);
    cudaGetSymbolAddress((void**)&bh, g_Bh);
    cudaGetSymbolAddress((void**)&bl, g_Bl);

    cudaFuncSetAttribute(k_mgemm<0,16,0>,  cudaFuncAttributeMaxDynamicSharedMemorySize, SMEM_MG);
    cudaFuncSetAttribute(k_mgemm<0,128,0>, cudaFuncAttributeMaxDynamicSharedMemorySize, SMEM_MG);
    cudaFuncSetAttribute(k_mgemm<1,128,1>, cudaFuncAttributeMaxDynamicSharedMemorySize, SMEM_MG);
    cudaFuncSetAttribute(k_mgemm<2,128,0>, cudaFuncAttributeMaxDynamicSharedMemorySize, SMEM_MG);

    const int GGRID = 296;   // 148 SMs x occupancy 2

    // prepw (with fused zeroing) must run before the CSR atomics
    {
        dim3 g((BIMG + 255) / 256, 17);
        k_prepw<<<g, 256>>>(W1_0, W1, W2, Wr1);
    }
    k_hist<<<(NE + 255) / 256, 256>>>(dstp);
    k_scan1<<<NB_SCAN, 256>>>();
    k_scan2<<<1, 512>>>();
    k_scan3<<<(NN + 255) / 256, 256>>>();
    k_fill<<<(NE + 255) / 256, 256>>>(srcp, dstp);

    for (int i = 0; i < NL; i++) {
        if (i == 0)
            k_agg0<<<(NN * 4 + 255) / 256, 256>>>(x, z0, eps);
        else
            k_agg<<<(NN * 32 + 255) / 256, 256>>>(hh, za, eps, i);

        const float* ba = (i == 0) ? b1_0 : (b1 + (size_t)(i - 1) * HIDD);
        int imgA = (i == 0) ? 0 : i;
        if (i == 0)
            k_mgemm<0,16,0><<<GGRID, 256, SMEM_MG>>>(z0, bh, bl, ba, y1,
                                                     (const float*)0, (const float*)0, 0, 0);
        else
            k_mgemm<0,128,0><<<GGRID, 256, SMEM_MG>>>(za, bh + (size_t)imgA * BIMG,
                                                      bl + (size_t)imgA * BIMG, ba, y1,
                                                      (const float*)0, (const float*)0, 0, i);

        int imgB = 8 + i;
        k_mgemm<1,128,1><<<GGRID, 256, SMEM_MG>>>(y1, bh + (size_t)imgB * BIMG,
                                                  bl + (size_t)imgB * BIMG,
                                                  b2 + (size_t)i * HIDD, zh,
                                                  g_in + (size_t)i * HIDD,
                                                  be_in + (size_t)i * HIDD, i, 8 + i);

        // skipmode: layer 1 -> store, layers 3/5 -> add, layer 7 -> add only (h unused after)
        int sm = (i % 2 == 1) ? ((i == 1) ? 1 : ((i == 7) ? 3 : 2)) : 0;
        k_post<<<(NN * 32 + 255) / 256, 256>>>(zh, hh, sm,
                                               g_out + (size_t)i * HIDD,
                                               be_out + (size_t)i * HIDD, 8 + i);
    }

    // regressor
    k_mgemm<2,128,0><<<GGRID, 256, SMEM_MG>>>(skip, bh + (size_t)16 * BIMG,
                                              bl + (size_t)16 * BIMG, br1, y1,
                                              (const float*)0, (const float*)0, 0, 16);
    k_final<<<(NN * 32 + 255) / 256, 256>>>(y1, Wr2, br2, gr, ber, (float*)d_out);
}